// round 6
// baseline (speedup 1.0000x reference)
#include <cuda_runtime.h>
#include <cstdint>

// CHIVE clockwork RNN scan — scalar, register-weights, cp.async-prefetch version.
// T=2048 serial steps, B=2048 batch, H=32. One warp per batch; lane = hidden j.
// All matvec weights in per-lane registers (no weight LDS). State in shared,
// read via broadcast LDS.128. Next active step's x prefetched via cp.async
// into a 2-slot shared stage. Active steps precompacted; lazy z-refresh flags.

#define TT 2048
#define BB 2048
#define HH 32
#define DF 8
#define DS 24
#define NW 2
#define NTHREADS (NW * 32)
#define NBLOCKS (BB / NW)          // 1024 CTAs

__device__ __forceinline__ float tanhap(float x) {
    float y; asm("tanh.approx.f32 %0, %1;" : "=f"(y) : "f"(x)); return y;
}

__device__ __forceinline__ void cp16(uint32_t dst, const float* src, bool pred) {
    asm volatile(
        "{ .reg .pred q; setp.ne.b32 q, %2, 0;"
        " @q cp.async.ca.shared.global [%0], [%1], 16; }"
        :: "r"(dst), "l"(src), "r"((int)pred));
}

__global__ __launch_bounds__(NTHREADS, 6)
void chive_kernel(const float* __restrict__ frnn,
                  const float* __restrict__ phrnn,
                  const float* __restrict__ syl,
                  const float* __restrict__ Wxf, const float* __restrict__ Whf,
                  const float* __restrict__ bfv,
                  const float* __restrict__ Wxp, const float* __restrict__ Whp,
                  const float* __restrict__ bpv,
                  const float* __restrict__ Wxs, const float* __restrict__ Whs,
                  const float* __restrict__ bsv,
                  const int* __restrict__ fclk, const int* __restrict__ pclk,
                  const int* __restrict__ sfreq,
                  float* __restrict__ out)
{
    __shared__ unsigned int slist[TT];            // packed (t<<8)|flags, compacted
    __shared__ unsigned char sflags[TT];
    __shared__ int snact;
    __shared__ __align__(16) float sh[NW][5][HH]; // hf, hp, hs0, hs1, hs2
    __shared__ __align__(16) float sxstage[NW][2][40]; // [0:8) fx, [8:16) px, [16:40) sx

    const int tid  = threadIdx.x;
    const int w    = tid >> 5;
    const int lane = tid & 31;
    const int b    = blockIdx.x * NW + w;

    // ---- phase 1: base update flags (bit0=f, bit1=p, bit2=s) ----
    for (int t = tid; t < TT; t += NTHREADS) {
        int uf = ((t % (fclk[t] + 1)) == 0) ? 1 : 0;
        int up = ((t % (pclk[t] + 1)) == 0) ? 2 : 0;
        int us = (sfreq[t] == 1) ? 4 : 0;
        sflags[t] = (unsigned char)(uf | up | us);
    }
    __syncthreads();

    // ---- phase 2: lazy z-refresh bits (bit3=f-refresh, bit4=p-refresh) ----
    // refresh needed at an f-update t iff an s-step consumes z before the next
    // f-update (same-step s counts as consume; same-step later f wins at u>t).
    unsigned mF = 0, mP = 0;
    {
        int c = 0;
        for (int t = tid; t < TT; t += NTHREADS, c++) {
            int f = sflags[t];
            if (f & 1) {
                int need = 1;
                if (!(f & 4)) {
                    for (int u = t + 1; u < TT; u++) {
                        int g = sflags[u];
                        if (g & 1) { need = 0; break; }   // f first -> later refresh covers it
                        if (g & 4) { need = 1; break; }   // s first -> must refresh now
                    }
                }
                if (need) mF |= 1u << c;
            }
            if (f & 2) {
                int need = 1;
                if (!(f & 4)) {
                    for (int u = t + 1; u < TT; u++) {
                        int g = sflags[u];
                        if (g & 2) { need = 0; break; }
                        if (g & 4) { need = 1; break; }
                    }
                }
                if (need) mP |= 1u << c;
            }
        }
    }
    __syncthreads();
    {
        int c = 0;
        for (int t = tid; t < TT; t += NTHREADS, c++) {
            int add = (int)((mF >> c) & 1) * 8 + (int)((mP >> c) & 1) * 16;
            if (add) sflags[t] |= (unsigned char)add;
        }
    }
    __syncthreads();

    // ---- phase 3: compact active steps (warp 0, ballot scan) ----
    if (w == 0) {
        int base = 0;
        for (int r = 0; r < TT / 32; r++) {
            int t = r * 32 + lane;
            int f = sflags[t];
            int act = (f & 7) ? 1 : 0;
            unsigned m = __ballot_sync(0xffffffff, act);
            int pos = base + __popc(m & ((1u << lane) - 1u));
            if (act) slist[pos] = ((unsigned)t << 8) | (unsigned)f;
            base += __popc(m);
        }
        if (lane == 0) snact = base;
    }
    // zero state
    for (int i = tid; i < NW * 5 * HH; i += NTHREADS)
        ((float*)sh)[i] = 0.0f;
    __syncthreads();

    // ---- per-lane register weights ----
    float whf[HH], whp[HH], whs[HH], wxs[HH], wxf[DF], wxp[DF];
#pragma unroll
    for (int k = 0; k < HH; k++) {
        whf[k] = Whf[k * HH + lane];
        whp[k] = Whp[k * HH + lane];
        whs[k] = Whs[k * HH + lane];
        wxs[k] = Wxs[k * HH + lane];
    }
#pragma unroll
    for (int k = 0; k < DF; k++) {
        wxf[k] = Wxf[k * HH + lane];
        wxp[k] = Wxp[k * HH + lane];
    }
    const float bf = bfv[lane];
    const float bp = bpv[lane];
    const float bs = bsv[lane];

    // ---- per-lane prefetch routing (lanes 0-9 carry the 3 x streams) ----
    const float* gb;
    long stepstr;
    int bit, dstoff;
    if (lane < 2)       { gb = frnn  + (size_t)b * DF + lane * 4;       stepstr = (long)BB * DF; bit = 1; dstoff = lane * 4; }
    else if (lane < 4)  { gb = phrnn + (size_t)b * DF + (lane - 2) * 4; stepstr = (long)BB * DF; bit = 2; dstoff = 8 + (lane - 2) * 4; }
    else if (lane < 10) { gb = syl   + (size_t)b * DS + (lane - 4) * 4; stepstr = (long)BB * DS; bit = 4; dstoff = 16 + (lane - 4) * 4; }
    else                { gb = frnn; stepstr = 0; bit = 0; dstoff = 0; }
    const uint32_t dst0 = (uint32_t)__cvta_generic_to_shared(&sxstage[w][0][dstoff]);
    const uint32_t dst1 = (uint32_t)__cvta_generic_to_shared(&sxstage[w][1][dstoff]);

    const float4* hf4 = (const float4*)sh[w][0];
    const float4* hp4 = (const float4*)sh[w][1];
    const float4* s04 = (const float4*)sh[w][2];
    const float4* s14 = (const float4*)sh[w][3];
    const float4* s24 = (const float4*)sh[w][4];

    float z0 = 0.0f, z1 = 0.0f;
    const int nact = snact;

    // pre-prefetch iter 0 into slot 0
    {
        unsigned e = slist[0];
        int tn = (int)(e >> 8);
        cp16(dst0, gb + (size_t)tn * stepstr, (e & (unsigned)bit) != 0);
    }
    asm volatile("cp.async.commit_group;" ::: "memory");

    for (int i = 0; i < nact; i++) {
        __syncwarp();                              // prior compute's stage reads done
        if (i + 1 < nact) {                        // prefetch i+1 into slot (i+1)&1
            unsigned e2 = slist[i + 1];
            int tn = (int)(e2 >> 8);
            uint32_t d = ((i + 1) & 1) ? dst1 : dst0;
            cp16(d, gb + (size_t)tn * stepstr, (e2 & (unsigned)bit) != 0);
        }
        asm volatile("cp.async.commit_group;" ::: "memory");
        asm volatile("cp.async.wait_group 1;" ::: "memory");  // slot i&1 landed
        __syncwarp();                              // cross-lane visibility of stage

        const unsigned e  = slist[i];
        const int fl      = (int)(e & 0xffu);
        const float* stg  = sxstage[w][i & 1];

        float hnf, hnp;
        // ---------------- f cell ----------------
        if (fl & 1) {
            const float4* x4 = (const float4*)stg;
            float4 xa = x4[0], xb = x4[1];
            float a0 = bf, a1 = 0.f;
#pragma unroll
            for (int q = 0; q < 8; q++) {
                float4 h = hf4[q];
                a0 = fmaf(h.x, whf[4 * q + 0], a0);
                a1 = fmaf(h.y, whf[4 * q + 1], a1);
                a0 = fmaf(h.z, whf[4 * q + 2], a0);
                a1 = fmaf(h.w, whf[4 * q + 3], a1);
            }
            a0 = fmaf(xa.x, wxf[0], a0); a1 = fmaf(xa.y, wxf[1], a1);
            a0 = fmaf(xa.z, wxf[2], a0); a1 = fmaf(xa.w, wxf[3], a1);
            a0 = fmaf(xb.x, wxf[4], a0); a1 = fmaf(xb.y, wxf[5], a1);
            a0 = fmaf(xb.z, wxf[6], a0); a1 = fmaf(xb.w, wxf[7], a1);
            hnf = tanhap(a0 + a1);
        }
        // ---------------- p cell ----------------
        if (fl & 2) {
            const float4* x4 = (const float4*)(stg + 8);
            float4 xa = x4[0], xb = x4[1];
            float a0 = bp, a1 = 0.f;
#pragma unroll
            for (int q = 0; q < 8; q++) {
                float4 h = hp4[q];
                a0 = fmaf(h.x, whp[4 * q + 0], a0);
                a1 = fmaf(h.y, whp[4 * q + 1], a1);
                a0 = fmaf(h.z, whp[4 * q + 2], a0);
                a1 = fmaf(h.w, whp[4 * q + 3], a1);
            }
            a0 = fmaf(xa.x, wxp[0], a0); a1 = fmaf(xa.y, wxp[1], a1);
            a0 = fmaf(xa.z, wxp[2], a0); a1 = fmaf(xa.w, wxp[3], a1);
            a0 = fmaf(xb.x, wxp[4], a0); a1 = fmaf(xb.y, wxp[5], a1);
            a0 = fmaf(xb.z, wxp[6], a0); a1 = fmaf(xb.w, wxp[7], a1);
            hnp = tanhap(a0 + a1);
        }
        if (fl & 3) {
            __syncwarp();                          // all lanes done reading old h
            if (fl & 1) sh[w][0][lane] = hnf;
            if (fl & 2) sh[w][1][lane] = hnp;
            __syncwarp();                          // new h visible warp-wide
        }
        // ---------------- lazy z refresh ----------------
        if (fl & 8) {
            float c0 = 0.f, c1 = 0.f;
#pragma unroll
            for (int q = 0; q < 8; q++) {
                float4 h = hf4[q];
                c0 = fmaf(h.x, wxs[4 * q + 0], c0);
                c1 = fmaf(h.y, wxs[4 * q + 1], c1);
                c0 = fmaf(h.z, wxs[4 * q + 2], c0);
                c1 = fmaf(h.w, wxs[4 * q + 3], c1);
            }
            z0 = c0 + c1;
        }
        if (fl & 16) {
            float c0 = 0.f, c1 = 0.f;
#pragma unroll
            for (int q = 0; q < 8; q++) {
                float4 h = hp4[q];
                c0 = fmaf(h.x, wxs[4 * q + 0], c0);
                c1 = fmaf(h.y, wxs[4 * q + 1], c1);
                c0 = fmaf(h.z, wxs[4 * q + 2], c0);
                c1 = fmaf(h.w, wxs[4 * q + 3], c1);
            }
            z1 = c0 + c1;
        }
        // ---------------- syl cell (3 slabs) ----------------
        if (fl & 4) {
            float p0 = bs + z0, q0 = 0.f;
            float p1 = bs + z1, q1 = 0.f;
            float p2 = bs,      q2 = 0.f;
#pragma unroll
            for (int q = 0; q < 8; q++) {
                float w0 = whs[4 * q + 0];
                float w1 = whs[4 * q + 1];
                float w2 = whs[4 * q + 2];
                float w3 = whs[4 * q + 3];
                float4 A = s04[q];
                p0 = fmaf(A.x, w0, p0); q0 = fmaf(A.y, w1, q0);
                p0 = fmaf(A.z, w2, p0); q0 = fmaf(A.w, w3, q0);
                float4 Bv = s14[q];
                p1 = fmaf(Bv.x, w0, p1); q1 = fmaf(Bv.y, w1, q1);
                p1 = fmaf(Bv.z, w2, p1); q1 = fmaf(Bv.w, w3, q1);
                float4 C = s24[q];
                p2 = fmaf(C.x, w0, p2); q2 = fmaf(C.y, w1, q2);
                p2 = fmaf(C.z, w2, p2); q2 = fmaf(C.w, w3, q2);
            }
            const float4* xs4 = (const float4*)(stg + 16);
#pragma unroll
            for (int q = 0; q < 6; q++) {          // only 24 real x cols
                float4 X = xs4[q];
                p2 = fmaf(X.x, wxs[4 * q + 0], p2);
                q2 = fmaf(X.y, wxs[4 * q + 1], q2);
                p2 = fmaf(X.z, wxs[4 * q + 2], p2);
                q2 = fmaf(X.w, wxs[4 * q + 3], q2);
            }
            float n0 = tanhap(p0 + q0);
            float n1 = tanhap(p1 + q1);
            float n2 = tanhap(p2 + q2);
            __syncwarp();                          // slab reads done before overwrite
            sh[w][2][lane] = n0;
            sh[w][3][lane] = n1;
            sh[w][4][lane] = n2;
        }
    }

    __syncwarp();
    // output: h_s [3, B, H]
    out[0 * BB * HH + b * HH + lane] = sh[w][2][lane];
    out[1 * BB * HH + b * HH + lane] = sh[w][3][lane];
    out[2 * BB * HH + b * HH + lane] = sh[w][4][lane];
}

extern "C" void kernel_launch(void* const* d_in, const int* in_sizes, int n_in,
                              void* d_out, int out_size) {
    const float* frnn  = (const float*)d_in[0];
    const float* phrnn = (const float*)d_in[1];
    const float* syl   = (const float*)d_in[2];
    const float* Wxf   = (const float*)d_in[3];
    const float* Whf   = (const float*)d_in[4];
    const float* bfv   = (const float*)d_in[5];
    const float* Wxp   = (const float*)d_in[6];
    const float* Whp   = (const float*)d_in[7];
    const float* bpv   = (const float*)d_in[8];
    const float* Wxs   = (const float*)d_in[9];
    const float* Whs   = (const float*)d_in[10];
    const float* bsv   = (const float*)d_in[11];
    const int*   fclk  = (const int*)d_in[12];
    const int*   pclk  = (const int*)d_in[13];
    const int*   sfreq = (const int*)d_in[14];
    float* out = (float*)d_out;

    chive_kernel<<<NBLOCKS, NTHREADS>>>(frnn, phrnn, syl,
                                        Wxf, Whf, bfv,
                                        Wxp, Whp, bpv,
                                        Wxs, Whs, bsv,
                                        fclk, pclk, sfreq, out);
}